// round 8
// baseline (speedup 1.0000x reference)
#include <cuda_runtime.h>
#include <cuda_bf16.h>
#include <math.h>

// Problem constants
#define BB   512
#define NN   101
#define EE   128
#define MM   8
#define DKK  16
#define TT   (BB * NN)        // 51712 = 404 * 128
#define FF   (4 * EE)         // 512
#define QKV  (3 * EE)         // 384
#define EPS  1e-5f

typedef unsigned long long ull;

// ---------------- device scratch ----------------
__device__ float g_x[TT * EE];
__device__ float g_qkv[TT * QKV];
__device__ float g_o[TT * EE];
__device__ float g_t[TT * EE];
__device__ float g_h[TT * FF];
__device__ float g_wqkv[3 * EE * QKV];
__device__ float g_bqkv[3 * QKV];
__device__ float g_ps [808 * EE];
__device__ float g_ps2[808 * EE];
__device__ float g_scale[EE];
__device__ float g_shift[EE];

// ---------------- f32x2 helpers ----------------
__device__ __forceinline__ ull fma2(ull a, ull b, ull c)
{
    ull d;
    asm("fma.rn.f32x2 %0, %1, %2, %3;" : "=l"(d) : "l"(a), "l"(b), "l"(c));
    return d;
}
__device__ __forceinline__ ull pack2(float x, float y)
{
    ull r;
    asm("mov.b64 %0, {%1, %2};" : "=l"(r) : "f"(x), "f"(y));
    return r;
}
__device__ __forceinline__ float2 unpack2(ull v)
{
    float2 r;
    asm("mov.b64 {%0, %1}, %2;" : "=f"(r.x), "=f"(r.y) : "l"(v));
    return r;
}
__device__ __forceinline__ unsigned smem_u32(const void* p)
{
    return (unsigned)__cvta_generic_to_shared(p);
}

// ---------------- embedding ----------------
__global__ void embed_kernel(const float* __restrict__ s, const int* __restrict__ d,
                             const float* __restrict__ e_w, const float* __restrict__ e_b,
                             const float* __restrict__ ep_w, const float* __restrict__ ep_b,
                             float* __restrict__ x)
{
    int idx = blockIdx.x * 256 + threadIdx.x;
    if (idx >= TT * EE) return;
    int e = idx & (EE - 1);
    int t = idx >> 7;
    int n = t % NN;
    int b = t / NN;
    float s0 = s[(b * NN + n) * 2 + 0];
    float s1 = s[(b * NN + n) * 2 + 1];
    float out;
    if (n == 0) {
        out = s0 * ep_w[e] + s1 * ep_w[EE + e] + ep_b[e];
    } else {
        float dd = (float)d[b * NN + n];
        out = s0 * e_w[e] + s1 * e_w[EE + e] + dd * e_w[2 * EE + e] + e_b[e];
    }
    x[idx] = out;
}

// ---------------- pack QKV weights ----------------
__global__ void pack_qkv(const float* __restrict__ Wq, const float* __restrict__ Wk,
                         const float* __restrict__ Wv, const float* __restrict__ bq,
                         const float* __restrict__ bk, const float* __restrict__ bv,
                         float* __restrict__ wout, float* __restrict__ bout)
{
    int idx = blockIdx.x * 256 + threadIdx.x;
    int total = 3 * EE * QKV;
    if (idx < total) {
        int i = idx / (EE * QKV);
        int r = idx % (EE * QKV);
        int k = r / QKV;
        int j = r % QKV;
        float v;
        if (j < EE)            v = Wq[(size_t)i * EE * EE + k * EE + j];
        else if (j < 2 * EE)   v = Wk[(size_t)i * EE * EE + k * EE + (j - EE)];
        else                   v = Wv[(size_t)i * EE * EE + k * EE + (j - 2 * EE)];
        wout[idx] = v;
    }
    if (idx < 3 * QKV) {
        int i = idx / QKV;
        int j = idx % QKV;
        float v;
        if (j < EE)            v = bq[i * EE + j];
        else if (j < 2 * EE)   v = bk[i * EE + (j - EE)];
        else                   v = bv[i * EE + (j - 2 * EE)];
        bout[idx] = v;
    }
}

// ---------------- GEMM v3: duplicated-A smem, cp.async B, f32x2 core -------
// C = affA(A) @ W + bias [+ affR(res) | relu]
#define BMt 128
#define BKt 32
#define AS_S 130                 // As2 row stride in u64 (16B-aligned rows)
#define SM_AS   (BKt * AS_S * 8)             // 33280 B
#define SM_BS   (2 * BKt * BMt * 4)          // 32768 B
#define SM_SA   (512 * 4)                    // 2048 B
#define SM_GEMM (SM_AS + SM_BS + 2 * SM_SA)  // 70144 B

__global__ __launch_bounds__(256, 2) void gemm_ep(
    const float* __restrict__ A, const float* __restrict__ W,
    const float* __restrict__ bias, const float* __restrict__ res,
    float* __restrict__ C, int K, int Nout, int mode,
    const float* __restrict__ sA, const float* __restrict__ hA,
    const float* __restrict__ sR, const float* __restrict__ hR)
{
    extern __shared__ char smem[];
    ull*   As2  = (ull*)smem;                          // [BKt][AS_S]
    float* Bs   = (float*)(smem + SM_AS);              // [2][BKt][BMt]
    float* sAsm = (float*)(smem + SM_AS + SM_BS);
    float* hAsm = (float*)(smem + SM_AS + SM_BS + SM_SA);

    const int t0 = blockIdx.y * BMt;
    const int n0 = blockIdx.x * BMt;
    const int tid = threadIdx.x;
    const int tx = tid & 15;
    const int ty = tid >> 4;

    // affine tables (identity if null)
    for (int i = tid; i < K; i += 256) {
        sAsm[i] = sA ? sA[i] : 1.0f;
        hAsm[i] = hA ? hA[i] : 0.0f;
    }

    ull acc[2][4][4];
    #pragma unroll
    for (int mq = 0; mq < 2; mq++)
        #pragma unroll
        for (int m = 0; m < 4; m++)
            #pragma unroll
            for (int p = 0; p < 4; p++)
                acc[mq][m][p] = pack2(0.f, 0.f);

    const int nk = K / BKt;

    // prologue: A tile 0 -> regs, B tile 0 -> smem stage 0 via cp.async
    float4 ra[4];
    #pragma unroll
    for (int p = 0; p < 4; p++) {
        int i = p * 256 + tid;
        int row = i >> 3, c4 = i & 7;
        ra[p] = *reinterpret_cast<const float4*>(&A[(size_t)(t0 + row) * K + c4 * 4]);
    }
    #pragma unroll
    for (int p = 0; p < 4; p++) {
        int i = p * 256 + tid;
        int row = i >> 5, c4 = i & 31;
        unsigned dst = smem_u32(&Bs[row * BMt + c4 * 4]);
        const float* src = &W[(size_t)row * Nout + n0 + c4 * 4];
        asm volatile("cp.async.ca.shared.global [%0], [%1], 16;" :: "r"(dst), "l"(src));
    }
    asm volatile("cp.async.commit_group;");

    for (int it = 0; it < nk; ++it) {
        const int k0 = it * BKt;
        const int s = it & 1;
        __syncthreads();   // previous compute done; As2 free (also covers sAsm on it==0)

        // store A tile (affine + transpose + duplicate)
        #pragma unroll
        for (int p = 0; p < 4; p++) {
            int i = p * 256 + tid;
            int row = i >> 3, c4 = i & 7;
            int kc = c4 * 4;
            float vx = fmaf(ra[p].x, sAsm[k0 + kc + 0], hAsm[k0 + kc + 0]);
            float vy = fmaf(ra[p].y, sAsm[k0 + kc + 1], hAsm[k0 + kc + 1]);
            float vz = fmaf(ra[p].z, sAsm[k0 + kc + 2], hAsm[k0 + kc + 2]);
            float vw = fmaf(ra[p].w, sAsm[k0 + kc + 3], hAsm[k0 + kc + 3]);
            As2[(kc + 0) * AS_S + row] = pack2(vx, vx);
            As2[(kc + 1) * AS_S + row] = pack2(vy, vy);
            As2[(kc + 2) * AS_S + row] = pack2(vz, vz);
            As2[(kc + 3) * AS_S + row] = pack2(vw, vw);
        }

        if (it + 1 < nk) {
            const int kn = k0 + BKt;
            #pragma unroll
            for (int p = 0; p < 4; p++) {
                int i = p * 256 + tid;
                int row = i >> 3, c4 = i & 7;
                ra[p] = *reinterpret_cast<const float4*>(&A[(size_t)(t0 + row) * K + kn + c4 * 4]);
            }
            const int sn = s ^ 1;
            #pragma unroll
            for (int p = 0; p < 4; p++) {
                int i = p * 256 + tid;
                int row = i >> 5, c4 = i & 31;
                unsigned dst = smem_u32(&Bs[sn * (BKt * BMt) + row * BMt + c4 * 4]);
                const float* src = &W[(size_t)(kn + row) * Nout + n0 + c4 * 4];
                asm volatile("cp.async.ca.shared.global [%0], [%1], 16;" :: "r"(dst), "l"(src));
            }
            asm volatile("cp.async.commit_group;");
            asm volatile("cp.async.wait_group 1;");
        } else {
            asm volatile("cp.async.wait_group 0;");
        }
        __syncthreads();

        const float* bsb = Bs + s * (BKt * BMt);
        #pragma unroll 8
        for (int kk = 0; kk < BKt; kk++) {
            const ulonglong2* ar0 = reinterpret_cast<const ulonglong2*>(As2 + kk * AS_S + ty * 4);
            const ulonglong2* ar1 = reinterpret_cast<const ulonglong2*>(As2 + kk * AS_S + 64 + ty * 4);
            ulonglong2 aA = ar0[0], aBv = ar0[1];
            ulonglong2 aC = ar1[0], aD = ar1[1];
            const float* bsk = bsb + kk * BMt;
            ulonglong2 b0 = *reinterpret_cast<const ulonglong2*>(bsk + tx * 4);
            ulonglong2 b1 = *reinterpret_cast<const ulonglong2*>(bsk + 64 + tx * 4);
            ull ap[8] = { aA.x, aA.y, aBv.x, aBv.y, aC.x, aC.y, aD.x, aD.y };
            ull bp[4] = { b0.x, b0.y, b1.x, b1.y };
            #pragma unroll
            for (int mq = 0; mq < 2; mq++)
                #pragma unroll
                for (int m = 0; m < 4; m++)
                    #pragma unroll
                    for (int p = 0; p < 4; p++)
                        acc[mq][m][p] = fma2(ap[mq * 4 + m], bp[p], acc[mq][m][p]);
        }
    }

    // epilogue
    #pragma unroll
    for (int cq = 0; cq < 2; cq++) {
        int col = n0 + cq * 64 + tx * 4;
        float4 b4 = *reinterpret_cast<const float4*>(&bias[col]);
        float4 sR4 = {1.f,1.f,1.f,1.f}, hR4 = {0.f,0.f,0.f,0.f};
        if (mode == 1 && sR) {
            sR4 = *reinterpret_cast<const float4*>(&sR[col]);
            hR4 = *reinterpret_cast<const float4*>(&hR[col]);
        }
        #pragma unroll
        for (int mq = 0; mq < 2; mq++) {
            #pragma unroll
            for (int m = 0; m < 4; m++) {
                int row = t0 + mq * 64 + ty * 4 + m;
                float2 lo = unpack2(acc[mq][m][cq * 2 + 0]);
                float2 hi = unpack2(acc[mq][m][cq * 2 + 1]);
                float4 v = { lo.x + b4.x, lo.y + b4.y, hi.x + b4.z, hi.y + b4.w };
                if (mode == 1) {
                    float4 r4 = *reinterpret_cast<const float4*>(&res[(size_t)row * Nout + col]);
                    v.x += fmaf(r4.x, sR4.x, hR4.x);
                    v.y += fmaf(r4.y, sR4.y, hR4.y);
                    v.z += fmaf(r4.z, sR4.z, hR4.z);
                    v.w += fmaf(r4.w, sR4.w, hR4.w);
                } else if (mode == 2) {
                    v.x = fmaxf(v.x, 0.f); v.y = fmaxf(v.y, 0.f);
                    v.z = fmaxf(v.z, 0.f); v.w = fmaxf(v.w, 0.f);
                }
                *reinterpret_cast<float4*>(&C[(size_t)row * Nout + col]) = v;
            }
        }
    }
}

// ---------------- attention v3: 2 heads/block, 2 queries/thread ------------
__global__ __launch_bounds__(128) void attn_kernel(
    const float* __restrict__ QKVb, float* __restrict__ O)
{
    int blk = blockIdx.x;            // 2048 blocks
    int b = blk >> 2;
    int hp = blk & 3;
    int tid = threadIdx.x;
    int hl = tid >> 6;               // head-local 0/1
    int t = tid & 63;
    int h = hp * 2 + hl;
    const size_t rowbase = (size_t)b * NN;
    const int hq = h * DKK;

    __shared__ float4 ksh[2][NN][4];
    __shared__ float4 vsh[2][NN][4];
    for (int i = t; i < NN * 4; i += 64) {
        int j = i >> 2, c = i & 3;
        ksh[hl][j][c] = *reinterpret_cast<const float4*>(&QKVb[(rowbase + j) * QKV + EE     + hq + c * 4]);
        vsh[hl][j][c] = *reinterpret_cast<const float4*>(&QKVb[(rowbase + j) * QKV + 2 * EE + hq + c * 4]);
    }
    __syncthreads();

    const int q0 = t;                       // always < NN
    const bool has2 = (t + 64 < NN);        // t < 37
    const int q1 = has2 ? t + 64 : 0;

    ull qp0[8], qp1[8];
    #pragma unroll
    for (int c = 0; c < 4; c++) {
        float4 a = *reinterpret_cast<const float4*>(&QKVb[(rowbase + q0) * QKV + hq + c * 4]);
        qp0[c * 2 + 0] = pack2(a.x * 0.25f, a.y * 0.25f);
        qp0[c * 2 + 1] = pack2(a.z * 0.25f, a.w * 0.25f);
        float4 d = *reinterpret_cast<const float4*>(&QKVb[(rowbase + q1) * QKV + hq + c * 4]);
        qp1[c * 2 + 0] = pack2(d.x * 0.25f, d.y * 0.25f);
        qp1[c * 2 + 1] = pack2(d.z * 0.25f, d.w * 0.25f);
    }
    const ull z2 = pack2(0.f, 0.f);
    ull oa0[8], oa1[8];
    #pragma unroll
    for (int c = 0; c < 8; c++) { oa0[c] = z2; oa1[c] = z2; }
    float l0 = 0.f, l1 = 0.f;

    for (int j = 0; j < NN; j++) {
        const ulonglong2* kr = reinterpret_cast<const ulonglong2*>(ksh[hl][j]);
        ulonglong2 ka = kr[0], kb = kr[1], kc = kr[2], kd = kr[3];
        ull kv[8] = { ka.x, ka.y, kb.x, kb.y, kc.x, kc.y, kd.x, kd.y };

        ull c0a = fma2(qp0[0], kv[0], z2);
        ull c0b = fma2(qp0[1], kv[1], z2);
        ull c1a = fma2(qp1[0], kv[0], z2);
        ull c1b = fma2(qp1[1], kv[1], z2);
        #pragma unroll
        for (int c = 1; c < 4; c++) {
            c0a = fma2(qp0[c * 2 + 0], kv[c * 2 + 0], c0a);
            c0b = fma2(qp0[c * 2 + 1], kv[c * 2 + 1], c0b);
            c1a = fma2(qp1[c * 2 + 0], kv[c * 2 + 0], c1a);
            c1b = fma2(qp1[c * 2 + 1], kv[c * 2 + 1], c1b);
        }
        float2 f0a = unpack2(c0a), f0b = unpack2(c0b);
        float2 f1a = unpack2(c1a), f1b = unpack2(c1b);
        float p0 = __expf((f0a.x + f0a.y) + (f0b.x + f0b.y));
        float p1 = __expf((f1a.x + f1a.y) + (f1b.x + f1b.y));
        l0 += p0; l1 += p1;

        const ulonglong2* vr = reinterpret_cast<const ulonglong2*>(vsh[hl][j]);
        ulonglong2 va = vr[0], vb = vr[1], vc = vr[2], vd = vr[3];
        ull vv[8] = { va.x, va.y, vb.x, vb.y, vc.x, vc.y, vd.x, vd.y };
        ull pp0 = pack2(p0, p0);
        ull pp1 = pack2(p1, p1);
        #pragma unroll
        for (int c = 0; c < 8; c++) {
            oa0[c] = fma2(pp0, vv[c], oa0[c]);
            oa1[c] = fma2(pp1, vv[c], oa1[c]);
        }
    }

    float inv0 = 1.0f / l0;
    float* orow0 = &O[(rowbase + q0) * EE + hq];
    #pragma unroll
    for (int c = 0; c < 4; c++) {
        float2 lo = unpack2(oa0[c * 2 + 0]);
        float2 hi = unpack2(oa0[c * 2 + 1]);
        float4 v = { lo.x * inv0, lo.y * inv0, hi.x * inv0, hi.y * inv0 };
        *reinterpret_cast<float4*>(&orow0[c * 4]) = v;
    }
    if (has2) {
        float inv1 = 1.0f / l1;
        float* orow1 = &O[(rowbase + q1) * EE + hq];
        #pragma unroll
        for (int c = 0; c < 4; c++) {
            float2 lo = unpack2(oa1[c * 2 + 0]);
            float2 hi = unpack2(oa1[c * 2 + 1]);
            float4 v = { lo.x * inv1, lo.y * inv1, hi.x * inv1, hi.y * inv1 };
            *reinterpret_cast<float4*>(&orow1[c * 4]) = v;
        }
    }
}

// ---------------- BatchNorm stats ----------------
#define BN_BLOCKS 808
#define ROWS_PER_BLK (TT / BN_BLOCKS)   // 64
__global__ __launch_bounds__(128) void bn_partial(const float* __restrict__ x,
                                                  float* __restrict__ psum,
                                                  float* __restrict__ psq)
{
    int e = threadIdx.x;
    int blk = blockIdx.x;
    int r0 = blk * ROWS_PER_BLK;
    float s = 0.f, s2 = 0.f;
    #pragma unroll 8
    for (int r = 0; r < ROWS_PER_BLK; r++) {
        float v = x[(size_t)(r0 + r) * EE + e];
        s += v; s2 += v * v;
    }
    psum[blk * EE + e] = s;
    psq [blk * EE + e] = s2;
}

__global__ __launch_bounds__(128) void bn_finalize(const float* __restrict__ psum,
                                                   const float* __restrict__ psq,
                                                   const float* __restrict__ g,
                                                   const float* __restrict__ be,
                                                   float* __restrict__ scale,
                                                   float* __restrict__ shift)
{
    int e = threadIdx.x;
    float s = 0.f, s2 = 0.f;
    #pragma unroll 8
    for (int i = 0; i < BN_BLOCKS; i++) { s += psum[i * EE + e]; s2 += psq[i * EE + e]; }
    float mu = s / (float)TT;
    float var = s2 / (float)TT - mu * mu;
    float sc = rsqrtf(var + EPS) * g[e];
    scale[e] = sc;
    shift[e] = be[e] - mu * sc;
}

__global__ __launch_bounds__(256) void bn_apply_final(const float* __restrict__ x,
                                                      const float* __restrict__ scale,
                                                      const float* __restrict__ shift,
                                                      float* __restrict__ y)
{
    int idx = blockIdx.x * 256 + threadIdx.x;
    if (idx >= TT * EE) return;
    int e = idx & (EE - 1);
    y[idx] = fmaf(x[idx], scale[e], shift[e]);
}

// ---------------- host orchestration ----------------
extern "C" void kernel_launch(void* const* d_in, const int* in_sizes, int n_in,
                              void* d_out, int out_size)
{
    const float* s    = (const float*)d_in[0];
    const int*   dd   = (const int*)  d_in[1];
    const float* e_w  = (const float*)d_in[2];
    const float* e_b  = (const float*)d_in[3];
    const float* ep_w = (const float*)d_in[4];
    const float* ep_b = (const float*)d_in[5];
    const float* Wq   = (const float*)d_in[6];
    const float* bq   = (const float*)d_in[7];
    const float* Wk   = (const float*)d_in[8];
    const float* bk   = (const float*)d_in[9];
    const float* Wv   = (const float*)d_in[10];
    const float* bv   = (const float*)d_in[11];
    const float* Wo   = (const float*)d_in[12];
    const float* bo   = (const float*)d_in[13];
    const float* Wf1  = (const float*)d_in[14];
    const float* bf1  = (const float*)d_in[15];
    const float* Wf2  = (const float*)d_in[16];
    const float* bf2  = (const float*)d_in[17];
    const float* g1   = (const float*)d_in[18];
    const float* be1  = (const float*)d_in[19];
    const float* g2   = (const float*)d_in[20];
    const float* be2  = (const float*)d_in[21];

    float *px, *pqkv, *po, *pt, *ph, *pwq, *pbq, *pps, *pps2, *pscale, *pshift;
    cudaGetSymbolAddress((void**)&px,     g_x);
    cudaGetSymbolAddress((void**)&pqkv,   g_qkv);
    cudaGetSymbolAddress((void**)&po,     g_o);
    cudaGetSymbolAddress((void**)&pt,     g_t);
    cudaGetSymbolAddress((void**)&ph,     g_h);
    cudaGetSymbolAddress((void**)&pwq,    g_wqkv);
    cudaGetSymbolAddress((void**)&pbq,    g_bqkv);
    cudaGetSymbolAddress((void**)&pps,    g_ps);
    cudaGetSymbolAddress((void**)&pps2,   g_ps2);
    cudaGetSymbolAddress((void**)&pscale, g_scale);
    cudaGetSymbolAddress((void**)&pshift, g_shift);

    static int smem_set = 0;
    if (!smem_set) {
        cudaFuncSetAttribute(gemm_ep, cudaFuncAttributeMaxDynamicSharedMemorySize, SM_GEMM);
        smem_set = 1;
    }

    const int elem_grid = (TT * EE) / 256;
    const dim3 gQKV(QKV / BMt, TT / BMt);   // (3, 404)
    const dim3 gE(EE / BMt, TT / BMt);      // (1, 404)
    const dim3 gF(FF / BMt, TT / BMt);      // (4, 404)

    embed_kernel<<<elem_grid, 256>>>(s, dd, e_w, e_b, ep_w, ep_b, px);
    pack_qkv<<<(3 * EE * QKV + 255) / 256, 256>>>(Wq, Wk, Wv, bq, bk, bv, pwq, pbq);

    const float* curS = nullptr;   // pending bn affine on current x (px)
    const float* curH = nullptr;

    for (int i = 0; i < 3; i++) {
        const float* Woi = Wo + (size_t)i * EE * EE;
        const float* W1i = Wf1 + (size_t)i * EE * FF;
        const float* W2i = Wf2 + (size_t)i * FF * EE;

        // qkv = bn(x) @ Wqkv + b
        gemm_ep<<<gQKV, 256, SM_GEMM>>>(px, pwq + (size_t)i * EE * QKV, pbq + i * QKV,
                                        nullptr, pqkv, EE, QKV, 0, curS, curH, nullptr, nullptr);
        attn_kernel<<<BB * MM / 2, 128>>>(pqkv, po);

        // t1 = o @ Wo + bo + bn(x)
        gemm_ep<<<gE, 256, SM_GEMM>>>(po, Woi, bo + i * EE, px, pt, EE, EE, 1,
                                      nullptr, nullptr, curS, curH);
        bn_partial<<<BN_BLOCKS, 128>>>(pt, pps, pps2);
        bn_finalize<<<1, 128>>>(pps, pps2, g1 + i * EE, be1 + i * EE, pscale, pshift);

        // h = relu(bn1(t1) @ Wf1 + bf1)
        gemm_ep<<<gF, 256, SM_GEMM>>>(pt, W1i, bf1 + i * FF, nullptr, ph, EE, FF, 2,
                                      pscale, pshift, nullptr, nullptr);
        // t2 = h @ Wf2 + bf2 + bn1(t1)
        gemm_ep<<<gE, 256, SM_GEMM>>>(ph, W2i, bf2 + i * EE, pt, px, FF, EE, 1,
                                      nullptr, nullptr, pscale, pshift);
        bn_partial<<<BN_BLOCKS, 128>>>(px, pps, pps2);
        bn_finalize<<<1, 128>>>(pps, pps2, g2 + i * EE, be2 + i * EE, pscale, pshift);
        curS = pscale; curH = pshift;
    }
    bn_apply_final<<<elem_grid, 256>>>(px, pscale, pshift, (float*)d_out);
    (void)in_sizes; (void)n_in; (void)out_size;
}